// round 1
// baseline (speedup 1.0000x reference)
#include <cuda_runtime.h>
#include <cuda_bf16.h>

// NeuSSampler inverse-CDF importance sampling.
// weights [R,128,1] f32, existing_bins [R,129] f32, nears [R,1], fars [R,1],
// num_samples (scalar int, fixed 64) -> out [R,65] f32.
//
// One warp per ray. 8 rays per 256-thread block.

#define S_SAMP 128
#define SP1 129            // S+1 cdf/bin entries
#define NB 65              // num_samples + 1 outputs per ray
#define HIST_PAD 1e-5f
#define EPS_V 1e-5f
#define WARPS_PER_BLOCK 8
#define NTHREADS (WARPS_PER_BLOCK * 32)
#define SM_STRIDE 132      // pad past 129 to stagger banks a bit

__global__ __launch_bounds__(NTHREADS)
void neus_sampler_kernel(const float* __restrict__ weights,
                         const float* __restrict__ ebins,
                         const float* __restrict__ nears,
                         const float* __restrict__ fars,
                         float* __restrict__ out,
                         int R)
{
    __shared__ float cdf_sm[WARPS_PER_BLOCK][SM_STRIDE];
    __shared__ float bin_sm[WARPS_PER_BLOCK][SM_STRIDE];

    const int warp = threadIdx.x >> 5;
    const int lane = threadIdx.x & 31;
    const int ray  = blockIdx.x * WARPS_PER_BLOCK + warp;
    if (ray >= R) return;

    // ---- 1. load 4 weights per lane (coalesced float4), local cumsum ----
    const float4 wv = *reinterpret_cast<const float4*>(
        weights + (size_t)ray * S_SAMP + lane * 4);
    const float w0 = wv.x + HIST_PAD;
    const float w1 = wv.y + HIST_PAD;
    const float w2 = wv.z + HIST_PAD;
    const float w3 = wv.w + HIST_PAD;
    const float l0 = w0;
    const float l1 = l0 + w1;
    const float l2 = l1 + w2;
    const float l3 = l2 + w3;

    // ---- 2. warp inclusive scan over per-lane sums ----
    float pre = l3;
    #pragma unroll
    for (int off = 1; off < 32; off <<= 1) {
        float v = __shfl_up_sync(0xffffffffu, pre, off);
        if (lane >= off) pre += v;
    }
    const float total = __shfl_sync(0xffffffffu, pre, 31);
    const float excl  = pre - l3;  // exclusive prefix of this lane's chunk

    // ---- 3. padding (exact reference semantics; ~always 0 here) ----
    const float padding = fmaxf(0.0f, EPS_V - total);
    const float inv_wsum = 1.0f / (total + padding);
    const float padper = padding * (1.0f / (float)S_SAMP);

    // cdf[k+1] = min(1, cumsum_{0..k}(w + pad/S) / wsum)
    const int k = lane * 4;
    float* cdfw = cdf_sm[warp];
    cdfw[k + 1] = fminf(1.0f, (excl + l0 + (float)(k + 1) * padper) * inv_wsum);
    cdfw[k + 2] = fminf(1.0f, (excl + l1 + (float)(k + 2) * padper) * inv_wsum);
    cdfw[k + 3] = fminf(1.0f, (excl + l2 + (float)(k + 3) * padper) * inv_wsum);
    cdfw[k + 4] = fminf(1.0f, (excl + l3 + (float)(k + 4) * padper) * inv_wsum);
    if (lane == 0) cdfw[0] = 0.0f;

    // ---- 4. stage existing bin edges (coalesced) ----
    const float* eb = ebins + (size_t)ray * SP1;
    float* binw = bin_sm[warp];
    for (int i = lane; i < SP1; i += 32) binw[i] = eb[i];

    const float nearv = nears[ray];
    const float farv  = fars[ray];
    __syncwarp();

    // ---- 5. 65 inverse-CDF queries: binary search + lerp ----
    float* orow = out + (size_t)ray * NB;
    for (int j = lane; j < NB; j += 32) {
        const float u = ((float)j + 0.5f) * (1.0f / (float)NB);

        // searchsorted(cdf, u, side='right'): first idx with cdf[idx] > u
        int lo = 0, hi = SP1;
        #pragma unroll
        while (lo < hi) {
            int mid = (lo + hi) >> 1;
            if (cdfw[mid] <= u) lo = mid + 1; else hi = mid;
        }
        int below = lo - 1;            // lo >= 1 since cdf[0]=0 <= u
        if (below > S_SAMP) below = S_SAMP;
        if (below < 0) below = 0;
        int above = lo;
        if (above > S_SAMP) above = S_SAMP;

        const float c0 = cdfw[below];
        const float c1 = cdfw[above];
        const float b0 = binw[below];
        const float b1 = binw[above];
        const float d  = c1 - c0;
        const float t  = (d > 0.0f)
                       ? fminf(fmaxf((u - c0) / d, 0.0f), 1.0f)
                       : 0.0f;
        const float b = b0 + t * (b1 - b0);
        orow[j] = b * farv + (1.0f - b) * nearv;
    }
}

extern "C" void kernel_launch(void* const* d_in, const int* in_sizes, int n_in,
                              void* d_out, int out_size) {
    const float* weights = (const float*)d_in[0];
    const float* ebins   = (const float*)d_in[1];
    const float* nears   = (const float*)d_in[2];
    const float* fars    = (const float*)d_in[3];
    // d_in[4] is num_samples (fixed at 64 -> 65 bins, compile-time constant)
    float* out = (float*)d_out;

    const int R = in_sizes[2];  // nears has R elements
    const int grid = (R + WARPS_PER_BLOCK - 1) / WARPS_PER_BLOCK;
    neus_sampler_kernel<<<grid, NTHREADS>>>(weights, ebins, nears, fars, out, R);
}

// round 3
// speedup vs baseline: 1.6000x; 1.6000x over previous
#include <cuda_runtime.h>
#include <cuda_bf16.h>

// NeuSSampler inverse-CDF importance sampling — scatter formulation.
// weights [R,128,1] f32, existing_bins [R,129] f32, nears [R,1], fars [R,1]
// -> out [R,65] f32.
//
// One warp per ray, fully register-resident (no shared memory, no search):
// since u_j = (j+0.5)/65 is a fixed uniform grid, CDF segment i owns queries
// j in [m_i, m_{i+1}) with m_k = ceil(65*cdf[k] - 0.5). Each lane holds 4
// segments; boundaries are shared with neighbors via shfl so the partition
// of {0..64} is exact (every output written exactly once).
//
// NOTE: existing_bins rows are 129 floats (516 B stride) — NOT 16B aligned,
// so bin edges are loaded with scalar 32-bit loads (same DRAM sectors).

#define S_SAMP 128
#define NB 65
#define HIST_PAD 1e-5f
#define EPS_V 1e-5f
#define WARPS_PER_BLOCK 8
#define NTHREADS (WARPS_PER_BLOCK * 32)

__device__ __forceinline__ int bnd(float c) {
    // first j with u_j >= c :  j >= 65*c - 0.5
    return (int)ceilf(fmaf(65.0f, c, -0.5f));
}

__global__ __launch_bounds__(NTHREADS)
void neus_sampler_kernel(const float* __restrict__ weights,
                         const float* __restrict__ ebins,
                         const float* __restrict__ nears,
                         const float* __restrict__ fars,
                         float* __restrict__ out,
                         int R)
{
    const int warp = threadIdx.x >> 5;
    const int lane = threadIdx.x & 31;
    const int ray  = blockIdx.x * WARPS_PER_BLOCK + warp;
    if (ray >= R) return;

    // ---- 1. load 4 weights per lane (coalesced float4, 512B-stride rows) ----
    const float4 wv = *reinterpret_cast<const float4*>(
        weights + (size_t)ray * S_SAMP + lane * 4);
    const float l0 = wv.x + HIST_PAD;
    const float l1 = l0 + (wv.y + HIST_PAD);
    const float l2 = l1 + (wv.z + HIST_PAD);
    const float l3 = l2 + (wv.w + HIST_PAD);

    // ---- 2. warp inclusive scan over per-lane chunk sums ----
    float pre = l3;
    #pragma unroll
    for (int off = 1; off < 32; off <<= 1) {
        float v = __shfl_up_sync(0xffffffffu, pre, off);
        if (lane >= off) pre += v;
    }
    const float total = __shfl_sync(0xffffffffu, pre, 31);
    const float excl  = pre - l3;

    // ---- 3. padding (reference semantics; ~always 0 for these inputs) ----
    const float padding  = fmaxf(0.0f, EPS_V - total);
    const float inv_wsum = 1.0f / (total + padding);
    const float padper   = padding * (1.0f / (float)S_SAMP);

    // CDF values this lane owns: indices k .. k+4, k = 4*lane
    const int k = lane * 4;
    float c[5];
    c[0] = fminf(1.0f, (excl      + (float)(k    ) * padper) * inv_wsum);
    c[1] = fminf(1.0f, (excl + l0 + (float)(k + 1) * padper) * inv_wsum);
    c[2] = fminf(1.0f, (excl + l1 + (float)(k + 2) * padper) * inv_wsum);
    c[3] = fminf(1.0f, (excl + l2 + (float)(k + 3) * padper) * inv_wsum);
    c[4] = fminf(1.0f, (excl + l3 + (float)(k + 4) * padper) * inv_wsum);

    // ---- 4. bin edges: 4 scalar loads (516 B row stride, unaligned for f4)
    //         + neighbor's first element via shfl ----
    const float* eb = ebins + (size_t)ray * (S_SAMP + 1) + k;
    float b[5];
    b[0] = __ldg(eb + 0);
    b[1] = __ldg(eb + 1);
    b[2] = __ldg(eb + 2);
    b[3] = __ldg(eb + 3);
    b[4] = __shfl_down_sync(0xffffffffu, b[0], 1);
    if (lane == 31) b[4] = __ldg(eb + 4);   // eb[128] global = last edge

    // ---- 5. query-ownership boundaries (exactly shared across lanes) ----
    int m[5];
    m[1] = bnd(c[1]);
    m[2] = bnd(c[2]);
    m[3] = bnd(c[3]);
    m[4] = (lane == 31) ? NB : bnd(c[4]);   // lane31 claims everything left
    m[0] = __shfl_up_sync(0xffffffffu, m[4], 1);
    if (lane == 0) m[0] = 0;

    const float nearv = nears[ray];
    const float farv  = fars[ray];
    float* orow = out + (size_t)ray * NB;

    // ---- 6. each segment writes its claimed queries ----
    #pragma unroll
    for (int s = 0; s < 4; s++) {
        const int jl = m[s], jh = m[s + 1];
        if (jl < jh) {
            const float c0   = c[s];
            const float d    = c[s + 1] - c0;
            const float invd = 1.0f / d;          // d > 0 whenever jl < jh
            const float b0   = b[s];
            const float db   = b[s + 1] - b0;
            for (int j = jl; j < jh; j++) {
                const float u  = ((float)j + 0.5f) * (1.0f / (float)NB);
                const float t  = fminf(fmaxf((u - c0) * invd, 0.0f), 1.0f);
                const float bb = fmaf(t, db, b0);
                orow[j] = bb * farv + (1.0f - bb) * nearv;
            }
        }
    }
}

extern "C" void kernel_launch(void* const* d_in, const int* in_sizes, int n_in,
                              void* d_out, int out_size) {
    const float* weights = (const float*)d_in[0];
    const float* ebins   = (const float*)d_in[1];
    const float* nears   = (const float*)d_in[2];
    const float* fars    = (const float*)d_in[3];
    float* out = (float*)d_out;

    const int R = in_sizes[2];  // nears has R elements
    const int grid = (R + WARPS_PER_BLOCK - 1) / WARPS_PER_BLOCK;
    neus_sampler_kernel<<<grid, NTHREADS>>>(weights, ebins, nears, fars, out, R);
}

// round 4
// speedup vs baseline: 1.6798x; 1.0499x over previous
#include <cuda_runtime.h>
#include <cuda_bf16.h>

// NeuSSampler inverse-CDF importance sampling — scatter formulation, v2.
// weights [R,128,1] f32, existing_bins [R,129] f32, nears [R,1], fars [R,1]
// -> out [R,65] f32.
//
// One warp per ray, register-resident. u_j=(j+0.5)/65 is a fixed grid, so
// CDF segment i owns queries j in [m_i, m_{i+1}), m_k = ceil(65*cdf[k]-0.5)
// = floor(65*cdf[k]+0.5). Histogram padding folded analytically into the
// boundary FMA (cumsum(w+p)[k] = cumsum(w)[k] + k*p). No clamps needed:
// ownership guarantees t in [0,1).

#define S_SAMP 128
#define NB 65
#define HIST_PAD 1e-5f
#define EPS_V 1e-5f
#define WARPS_PER_BLOCK 8
#define NTHREADS (WARPS_PER_BLOCK * 32)
#define INV_NB (1.0f / 65.0f)

__global__ __launch_bounds__(NTHREADS)
void neus_sampler_kernel(const float* __restrict__ weights,
                         const float* __restrict__ ebins,
                         const float* __restrict__ nears,
                         const float* __restrict__ fars,
                         float* __restrict__ out,
                         int R)
{
    const int warp = threadIdx.x >> 5;
    const int lane = threadIdx.x & 31;
    const int ray  = blockIdx.x * WARPS_PER_BLOCK + warp;
    if (ray >= R) return;

    // ---- 1. raw cumsum of 4 weights (pad folded in later) ----
    const float4 wv = *reinterpret_cast<const float4*>(
        weights + (size_t)ray * S_SAMP + lane * 4);
    const float l0 = wv.x;
    const float l1 = l0 + wv.y;
    const float l2 = l1 + wv.z;
    const float l3 = l2 + wv.w;

    // ---- 2. warp inclusive scan over raw chunk sums ----
    float pre = l3;
    #pragma unroll
    for (int off = 1; off < 32; off <<= 1) {
        float v = __shfl_up_sync(0xffffffffu, pre, off);
        if (lane >= off) pre += v;
    }
    const float total_raw = __shfl_sync(0xffffffffu, pre, 31);
    const float excl      = pre - l3;

    // ---- 3. padding folded into a single per-index step ----
    const float total_wp = total_raw + (float)S_SAMP * HIST_PAD;
    const float padding  = fmaxf(0.0f, EPS_V - total_wp);
    const float inv_wsum = __fdividef(1.0f, total_wp + padding);
    const float step     = HIST_PAD + padding * (1.0f / (float)S_SAMP);

    // cdf[k+i] = (excl + l_{i-1} + (k+i)*step) * inv_wsum   (k = 4*lane)
    const int k = lane * 4;
    const float kf = (float)k;
    float c[5];
    c[0] = fmaf(kf,        step, excl     ) * inv_wsum;
    c[1] = fmaf(kf + 1.0f, step, excl + l0) * inv_wsum;
    c[2] = fmaf(kf + 2.0f, step, excl + l1) * inv_wsum;
    c[3] = fmaf(kf + 3.0f, step, excl + l2) * inv_wsum;
    c[4] = fmaf(kf + 4.0f, step, excl + l3) * inv_wsum;

    // ---- 4. bin edges (516B row stride: scalar loads) ----
    const float* eb = ebins + (size_t)ray * (S_SAMP + 1) + k;
    float b[5];
    b[0] = __ldg(eb + 0);
    b[1] = __ldg(eb + 1);
    b[2] = __ldg(eb + 2);
    b[3] = __ldg(eb + 3);
    b[4] = __shfl_down_sync(0xffffffffu, b[0], 1);
    if (lane == 31) b[4] = __ldg(eb + 4);

    // ---- 5. ownership boundaries: m = floor(65*c + 0.5) ----
    int m[5];
    m[1] = __float2int_rd(fmaf(65.0f, c[1], 0.5f));
    m[2] = __float2int_rd(fmaf(65.0f, c[2], 0.5f));
    m[3] = __float2int_rd(fmaf(65.0f, c[3], 0.5f));
    m[4] = __float2int_rd(fmaf(65.0f, c[4], 0.5f));  // lane31: c~1 -> 65
    m[0] = __shfl_up_sync(0xffffffffu, m[4], 1);
    if (lane == 0) m[0] = 0;

    const float nearv = nears[ray];
    const float dfn   = fars[ray] - nearv;
    float* orow = out + (size_t)ray * NB;

    // ---- 6. emit claimed queries (t in [0,1) by construction) ----
    #pragma unroll
    for (int s = 0; s < 4; s++) {
        const int jl = m[s], jh = m[s + 1];
        if (jl < jh) {
            const float c0    = c[s];
            const float invd  = __fdividef(1.0f, c[s + 1] - c0);
            const float base  = fmaf(b[s], dfn, nearv);
            const float scale = (b[s + 1] - b[s]) * dfn;
            // t_j = (u_j - c0)*invd, advanced incrementally
            float v  = (fmaf((float)jl, INV_NB, 0.5f * INV_NB) - c0) * invd;
            const float dv = INV_NB * invd;
            for (int j = jl; j < jh; j++) {
                orow[j] = fmaf(v, scale, base);
                v += dv;
            }
        }
    }
}

extern "C" void kernel_launch(void* const* d_in, const int* in_sizes, int n_in,
                              void* d_out, int out_size) {
    const float* weights = (const float*)d_in[0];
    const float* ebins   = (const float*)d_in[1];
    const float* nears   = (const float*)d_in[2];
    const float* fars    = (const float*)d_in[3];
    float* out = (float*)d_out;

    const int R = in_sizes[2];  // nears has R elements
    const int grid = (R + WARPS_PER_BLOCK - 1) / WARPS_PER_BLOCK;
    neus_sampler_kernel<<<grid, NTHREADS>>>(weights, ebins, nears, fars, out, R);
}